// round 12
// baseline (speedup 1.0000x reference)
#include <cuda_runtime.h>
#include <cuda_bf16.h>
#include <cstdint>
#include <math.h>

// ---------------------------------------------------------------- constants
constexpr int B_   = 32;
constexpr int H_   = 56;
constexpr int W_   = 56;
constexpr int C_   = 192;
constexpr int NH_  = 6;
constexpr int WS_  = 7;
constexpr int SS_  = 3;
constexpr int N_   = 49;
constexpr int HD_  = 32;
constexpr int NWH  = 8;
constexpr int NW_  = 64;
constexpr int HID_ = 768;
constexpr int TOK  = B_ * H_ * W_;   // 100352
constexpr int WINS = B_ * NW_;       // 2048
constexpr int C3   = 3 * C_;         // 576

// GEMM tiling (mma.sync m16n8k16 bf16): 128x96 CTA, 64x24 warp tile, BK=64
constexpr int BM = 128;
constexpr int BN = 96;
constexpr int BK = 64;
constexpr int PITCH = 72;
constexpr int A_STAGE = BM * PITCH;
constexpr int B_STAGE = BN * PITCH;
constexpr int SMEM_BYTES = 2 * (A_STAGE + B_STAGE) * 2;   // 64512

// attention (per-window) smem layout
constexpr int SQ_P    = 392;                   // q+k staged pitch (196 words ≡ 4 mod 32)
constexpr int OFF_SQ  = 0;                     // 49 x 392 (q cols 0-191, k cols 192-383)
constexpr int OFF_VT  = 49 * SQ_P;             // 19208 ; 6 heads x [32][72]
constexpr int VT_HEAD = 32 * 72;               // 2304
constexpr int OFF_P   = OFF_VT + NH_ * VT_HEAD;// 33032 ; 64 x 72
constexpr int AB_UNITS = OFF_P + 64 * 72;      // 37640 bf16 units
constexpr int AB_BYTES = AB_UNITS * 2;         // 75280
constexpr int SC_FLOATS  = 64 * 52;            // 3328
constexpr int RPB_FLOATS = 169 * NH_;          // 1014
constexpr int OFF_SC   = AB_BYTES;                         // float
constexpr int OFF_RPB  = OFF_SC + SC_FLOATS * 4;           // 88592
constexpr int OFF_MSK  = OFF_RPB + RPB_FLOATS * 4;         // 92648 (bf16 49x52)
constexpr int OFF_REL  = OFF_MSK + 49 * 52 * 2;            // 97744 (u8 49x50)
constexpr int ATT_SMEM = ((OFF_REL + 49 * 50 + 15) / 16) * 16;  // ~100208

// ---------------------------------------------------------------- scratch
__device__ __nv_bfloat16 g_hwin[(size_t)TOK * C_];
__device__ __nv_bfloat16 g_qkv[(size_t)TOK * C3];
__device__ __nv_bfloat16 g_attno[(size_t)TOK * C_];
__device__ float         g_x1[(size_t)TOK * C_];
__device__ __nv_bfloat16 g_ln2[(size_t)TOK * C_];
__device__ __nv_bfloat16 g_hid[(size_t)TOK * HID_];
__device__ __nv_bfloat16 g_qkvwT[(size_t)C3 * C_];
__device__ __nv_bfloat16 g_projT[(size_t)C_ * C_];
__device__ __nv_bfloat16 g_fc1T[(size_t)HID_ * C_];
__device__ __nv_bfloat16 g_fc2T[(size_t)C_ * HID_];

// ---------------------------------------------------------------- helpers
__device__ __forceinline__ uint32_t smem_u32(const void* p) {
    uint32_t a;
    asm("{ .reg .u64 t; cvta.to.shared.u64 t, %1; cvt.u32.u64 %0, t; }"
        : "=r"(a) : "l"(p));
    return a;
}
#define CP_ASYNC16(dst_u32, src_ptr) \
    asm volatile("cp.async.ca.shared.global [%0], [%1], 16;" \
        :: "r"(dst_u32), "l"(src_ptr) : "memory")
#define CP_ASYNC_COMMIT() asm volatile("cp.async.commit_group;" ::: "memory")
#define CP_ASYNC_WAIT_1() asm volatile("cp.async.wait_group 1;" ::: "memory")
#define CP_ASYNC_WAIT_0() asm volatile("cp.async.wait_group 0;" ::: "memory")

__device__ __forceinline__ void mma_bf16(
    float* d, const uint32_t* a, const uint32_t* b)
{
    asm volatile(
        "mma.sync.aligned.m16n8k16.row.col.f32.bf16.bf16.f32 "
        "{%0,%1,%2,%3}, {%4,%5,%6,%7}, {%8,%9}, {%0,%1,%2,%3};"
        : "+f"(d[0]), "+f"(d[1]), "+f"(d[2]), "+f"(d[3])
        : "r"(a[0]), "r"(a[1]), "r"(a[2]), "r"(a[3]),
          "r"(b[0]), "r"(b[1]));
}
__device__ __forceinline__ void ldsm_x4(uint32_t* r, uint32_t addr) {
    asm volatile("ldmatrix.sync.aligned.m8n8.x4.shared.b16 {%0,%1,%2,%3}, [%4];"
        : "=r"(r[0]), "=r"(r[1]), "=r"(r[2]), "=r"(r[3]) : "r"(addr));
}
__device__ __forceinline__ void ldsm_x2(uint32_t* r, uint32_t addr) {
    asm volatile("ldmatrix.sync.aligned.m8n8.x2.shared.b16 {%0,%1}, [%2];"
        : "=r"(r[0]), "=r"(r[1]) : "r"(addr));
}

// --------------------------------------------- merged weight prep (1 launch)
__global__ void wprep_all(
    const float* __restrict__ qkvw, const float* __restrict__ projw,
    const float* __restrict__ fc1w, const float* __restrict__ fc2w,
    __nv_bfloat16* __restrict__ qkvwT, __nv_bfloat16* __restrict__ projT,
    __nv_bfloat16* __restrict__ fc1T,  __nv_bfloat16* __restrict__ fc2T)
{
    __shared__ float t[32][33];
    int b = blockIdx.x;
    const float* src; __nv_bfloat16* dst; int K, N, t0;
    if (b < 108)      { src = qkvw; dst = qkvwT; K = 192; N = 576; t0 = b; }
    else if (b < 144) { src = projw; dst = projT; K = 192; N = 192; t0 = b - 108; }
    else if (b < 288) { src = fc1w; dst = fc1T; K = 192; N = 768; t0 = b - 144; }
    else              { src = fc2w; dst = fc2T; K = 768; N = 192; t0 = b - 288; }
    int ntiles = N / 32;
    int kb = (t0 / ntiles) * 32, nb = (t0 % ntiles) * 32;
    int x = threadIdx.x, y = threadIdx.y;
    for (int i = y; i < 32; i += 8)
        t[i][x] = src[(size_t)(kb + i) * N + nb + x];
    __syncthreads();
    for (int i = y; i < 32; i += 8)
        dst[(size_t)(nb + i) * K + kb + x] = __float2bfloat16_rn(t[x][i]);
}

// ---------------------------------------------------------------- LayerNorm
template <int PART>
__global__ void __launch_bounds__(256) ln_kernel(
    const float* __restrict__ src, __nv_bfloat16* __restrict__ dst,
    const float* __restrict__ gamma, const float* __restrict__ beta)
{
    int warp = threadIdx.x >> 5;
    int lane = threadIdx.x & 31;
    int t = blockIdx.x * 8 + warp;
    if (t >= TOK) return;

    const float* xr = src + (size_t)t * C_;
    float v[6];
    float s = 0.f;
#pragma unroll
    for (int i = 0; i < 6; i++) { v[i] = xr[lane + 32 * i]; s += v[i]; }
#pragma unroll
    for (int o = 16; o; o >>= 1) s += __shfl_xor_sync(0xffffffffu, s, o);
    float mean = s * (1.f / 192.f);
    float ss = 0.f;
#pragma unroll
    for (int i = 0; i < 6; i++) { float d = v[i] - mean; ss += d * d; }
#pragma unroll
    for (int o = 16; o; o >>= 1) ss += __shfl_xor_sync(0xffffffffu, ss, o);
    float rstd = rsqrtf(ss * (1.f / 192.f) + 1e-5f);

    int dt = t;
    if (PART) {
        int bb = t / (H_ * W_);
        int rem = t - bb * (H_ * W_);
        int h = rem / W_, w = rem - (rem / W_) * W_;
        int hs = h - SS_; if (hs < 0) hs += H_;
        int ws = w - SS_; if (ws < 0) ws += W_;
        int wl = (hs / WS_) * NWH + (ws / WS_);
        int n  = (hs % WS_) * WS_ + (ws % WS_);
        dt = bb * (NW_ * N_) + wl * N_ + n;
    }
    __nv_bfloat16* o = dst + (size_t)dt * C_;
#pragma unroll
    for (int i = 0; i < 6; i++) {
        int c = lane + 32 * i;
        o[c] = __float2bfloat16_rn((v[i] - mean) * rstd * gamma[c] + beta[c]);
    }
}

// ---------------------------------------------------------------- bf16 GEMM
template <int EPI>
__global__ void __launch_bounds__(256) gemm_mma(
    const __nv_bfloat16* __restrict__ A, const __nv_bfloat16* __restrict__ Bt,
    const float* __restrict__ bias, const float* __restrict__ add,
    void* __restrict__ Cout, int M, int N, int K)
{
    extern __shared__ __align__(16) __nv_bfloat16 smem[];
    __nv_bfloat16* Asm = smem;
    __nv_bfloat16* Bsm = smem + 2 * A_STAGE;

    const int tid  = threadIdx.x;
    const int wid  = tid >> 5;
    const int lane = tid & 31;
    const int wm   = wid >> 2;
    const int wn   = wid & 3;
    const int lr   = lane >> 2;
    const int lc   = lane & 3;
    const int bm   = blockIdx.x * BM;
    const int bn   = blockIdx.y * BN;
    const int nk   = K / BK;

    const int lj   = lane >> 3;
    const int lrow = lane & 7;
    const int a_m  = (lj & 1) * 8 + lrow;
    const int a_k  = (lj >> 1) * 8;
    const int b_k  = (lj & 1) * 8;

    float acc[4][3][4];
#pragma unroll
    for (int i = 0; i < 4; i++)
#pragma unroll
        for (int j = 0; j < 3; j++)
#pragma unroll
            for (int q = 0; q < 4; q++) acc[i][j][q] = 0.f;

    uint32_t asb = smem_u32(Asm);
    uint32_t bsb = smem_u32(Bsm);

    auto load_tile = [&](int k0, int st) {
#pragma unroll
        for (int i = tid; i < 1024; i += 256) {
            int m   = i >> 3;
            int k16 = i & 7;
            const __nv_bfloat16* src = A + (size_t)(bm + m) * K + k0 * BK + k16 * 8;
            uint32_t dst = asb + (uint32_t)(st * A_STAGE + m * PITCH + k16 * 8) * 2;
            CP_ASYNC16(dst, src);
        }
#pragma unroll
        for (int i = tid; i < 768; i += 256) {
            int n   = i >> 3;
            int k16 = i & 7;
            const __nv_bfloat16* src = Bt + (size_t)(bn + n) * K + k0 * BK + k16 * 8;
            uint32_t dst = bsb + (uint32_t)(st * B_STAGE + n * PITCH + k16 * 8) * 2;
            CP_ASYNC16(dst, src);
        }
        CP_ASYNC_COMMIT();
    };

    load_tile(0, 0);

    for (int k0 = 0; k0 < nk; k0++) {
        if (k0 + 1 < nk) { load_tile(k0 + 1, (k0 + 1) & 1); CP_ASYNC_WAIT_1(); }
        else             { CP_ASYNC_WAIT_0(); }
        __syncthreads();

        uint32_t asb_st = asb + (uint32_t)((k0 & 1) * A_STAGE) * 2;
        uint32_t bsb_st = bsb + (uint32_t)((k0 & 1) * B_STAGE) * 2;
#pragma unroll
        for (int ks = 0; ks < 4; ks++) {
            uint32_t a[4][4];
#pragma unroll
            for (int mi = 0; mi < 4; mi++) {
                uint32_t addr = asb_st +
                    (uint32_t)((wm * 64 + mi * 16 + a_m) * PITCH + ks * 16 + a_k) * 2;
                ldsm_x4(a[mi], addr);
            }
            uint32_t b[3][2];
#pragma unroll
            for (int ni = 0; ni < 3; ni++) {
                uint32_t addr = bsb_st +
                    (uint32_t)((wn * 24 + ni * 8 + lrow) * PITCH + ks * 16 + b_k) * 2;
                ldsm_x2(b[ni], addr);
            }
#pragma unroll
            for (int mi = 0; mi < 4; mi++)
#pragma unroll
                for (int ni = 0; ni < 3; ni++)
                    mma_bf16(acc[mi][ni], a[mi], b[ni]);
        }
        __syncthreads();
    }

#pragma unroll
    for (int mi = 0; mi < 4; mi++) {
#pragma unroll
        for (int half = 0; half < 2; half++) {
            int row = bm + wm * 64 + mi * 16 + lr + half * 8;
            int orow = row;
            if (EPI == 1) {
                int win = row / N_, n = row - win * N_;
                int b = win >> 6, wl = win & 63;
                int hs = (wl >> 3) * WS_ + n / WS_;
                int ws = (wl & 7) * WS_ + (n - (n / WS_) * WS_);
                int h = hs + SS_; if (h >= H_) h -= H_;
                int w = ws + SS_; if (w >= W_) w -= W_;
                orow = (b * H_ + h) * W_ + w;
            }
#pragma unroll
            for (int ni = 0; ni < 3; ni++) {
                int c = bn + wn * 24 + ni * 8 + 2 * lc;
                float2 bv = *(const float2*)(bias + c);
                float vx = acc[mi][ni][half * 2 + 0] + bv.x;
                float vy = acc[mi][ni][half * 2 + 1] + bv.y;
                if (EPI == 1) {
                    float2 av = *(const float2*)(add + (size_t)orow * N + c);
                    vx += av.x; vy += av.y;
                }
                if (EPI == 2) { vx *= normcdff(vx); vy *= normcdff(vy); }
                if (EPI == 3) {
                    float2 av = *(const float2*)(add + (size_t)row * N + c);
                    vx += av.x; vy += av.y;
                }
                if (EPI == 0 || EPI == 2) {
                    __nv_bfloat16* Co = (__nv_bfloat16*)Cout;
                    *(__nv_bfloat162*)(Co + (size_t)orow * N + c) =
                        __floats2bfloat162_rn(vx, vy);
                } else {
                    float* Co = (float*)Cout;
                    *(float2*)(Co + (size_t)orow * N + c) = make_float2(vx, vy);
                }
            }
        }
    }
}

// ---------------------------------------------------------------- attention
// One block per WINDOW, 256 threads, 6 head-phases.  rel-index (u8) and
// mask (bf16, exact) staged once per block; softmax bias = pure LDS.
__global__ void __launch_bounds__(256) attn_kernel(
    const float* __restrict__ rpb, const float* __restrict__ mask)
{
    extern __shared__ __align__(16) unsigned char dsm[];
    __nv_bfloat16* ab   = (__nv_bfloat16*)dsm;
    float*         sc   = (float*)(dsm + OFF_SC);
    float*         rpbs = (float*)(dsm + OFF_RPB);
    __nv_bfloat16* mskS = (__nv_bfloat16*)(dsm + OFF_MSK);
    uint8_t*       rel8 = (uint8_t*)(dsm + OFF_REL);

    int win  = blockIdx.x;
    int tid  = threadIdx.x;
    int warp = tid >> 5;
    int lane = tid & 31;

    // phase 1: zero vT+P (pads must be 0), stage rpb + rel table
    {
        uint32_t* zw = (uint32_t*)(ab + OFF_VT);
        for (int i = tid; i < (AB_UNITS - OFF_VT) / 2; i += 256) zw[i] = 0u;
    }
    for (int i = tid; i < RPB_FLOATS; i += 256) {
        int r = i / NH_, h = i - (i / NH_) * NH_;
        rpbs[h * 169 + r] = rpb[i];
    }
    for (int i = tid; i < N_ * N_; i += 256) {
        int n = i / N_, m = i - (i / N_) * N_;
        int i1 = n / WS_, j1 = n - i1 * WS_;
        int i2 = m / WS_, j2 = m - i2 * WS_;
        rel8[n * 50 + m] = (uint8_t)((i1 - i2 + WS_ - 1) * (2 * WS_ - 1)
                                     + (j1 - j2 + WS_ - 1));
    }
    __syncthreads();

    // phase 2: stage q,k rows (uint4), mask (bf16, exact), scatter v -> vT
    const __nv_bfloat16* base = g_qkv + (size_t)win * N_ * C3;
    for (int i = tid; i < N_ * 48; i += 256) {
        int n = i / 48, c8 = i - (i / 48) * 48;
        uint4 v = *(const uint4*)(base + (size_t)n * C3 + c8 * 8);
        *(uint4*)(ab + OFF_SQ + n * SQ_P + c8 * 8) = v;
    }
    const float* mrow = mask + (size_t)(win & (NW_ - 1)) * N_ * N_;
    for (int i = tid; i < N_ * N_; i += 256) {
        int n = i / N_, m = i - (i / N_) * N_;
        mskS[n * 52 + m] = __float2bfloat16_rn(mrow[i]);
    }
    for (int i = tid; i < N_ * 24; i += 256) {
        int n = i / 24, c8 = i - (i / 24) * 24;
        int c = c8 * 8;
        uint4 v = *(const uint4*)(base + (size_t)n * C3 + 2 * C_ + c);
        __nv_bfloat16 tmp[8];
        *(uint4*)tmp = v;
        int h = c >> 5, d0 = c & 31;
#pragma unroll
        for (int j = 0; j < 8; j++)
            ab[OFF_VT + h * VT_HEAD + (d0 + j) * 72 + n] = tmp[j];
    }
    __syncthreads();

    const int lj   = lane >> 3;
    const int lrow = lane & 7;
    const int a_m  = (lj & 1) * 8 + lrow;
    const int a_k  = (lj >> 1) * 8;
    const int b_k  = (lj & 1) * 8;
    const int lr   = lane >> 2;
    const int lc   = lane & 3;
    const int wr   = warp & 3;
    const int wc   = warp >> 2;

    uint32_t sqb = smem_u32(ab + OFF_SQ);
    uint32_t psb = smem_u32(ab + OFF_P);
    const float scale = 0.17677669529663687f;

    for (int h = 0; h < NH_; h++) {
        // ---- QK^T
        {
            float c[4][4];
#pragma unroll
            for (int i = 0; i < 4; i++)
#pragma unroll
                for (int q = 0; q < 4; q++) c[i][q] = 0.f;
#pragma unroll
            for (int ks = 0; ks < 2; ks++) {
                uint32_t a[4];
                ldsm_x4(a, sqb + (uint32_t)((wr * 16 + a_m) * SQ_P
                                            + h * HD_ + ks * 16 + a_k) * 2);
#pragma unroll
                for (int ni = 0; ni < 4; ni++) {
                    uint32_t b[2];
                    ldsm_x2(b, sqb + (uint32_t)((wc * 32 + ni * 8 + lrow) * SQ_P
                                                + C_ + h * HD_ + ks * 16 + b_k) * 2);
                    mma_bf16(c[ni], a, b);
                }
            }
#pragma unroll
            for (int ni = 0; ni < 4; ni++) {
                int col = wc * 32 + ni * 8 + 2 * lc;
                sc[(wr * 16 + lr) * 52 + col]           = c[ni][0];
                sc[(wr * 16 + lr) * 52 + col + 1]       = c[ni][1];
                sc[(wr * 16 + lr + 8) * 52 + col]       = c[ni][2];
                sc[(wr * 16 + lr + 8) * 52 + col + 1]   = c[ni][3];
            }
        }
        __syncthreads();

        // ---- softmax (all bias terms via LDS lookups)
        const float* rp = rpbs + h * 169;
        for (int n = warp; n < N_; n += 8) {
            float v0 = -1e30f, v1 = -1e30f;
            {
                int m = lane;
                v0 = sc[n * 52 + m] * scale + rp[rel8[n * 50 + m]]
                   + __bfloat162float(mskS[n * 52 + m]);
            }
            if (lane + 32 < N_) {
                int m = lane + 32;
                v1 = sc[n * 52 + m] * scale + rp[rel8[n * 50 + m]]
                   + __bfloat162float(mskS[n * 52 + m]);
            }
            float mx = fmaxf(v0, v1);
#pragma unroll
            for (int o = 16; o; o >>= 1) mx = fmaxf(mx, __shfl_xor_sync(0xffffffffu, mx, o));
            float e0 = __expf(v0 - mx);
            float e1 = (lane + 32 < N_) ? __expf(v1 - mx) : 0.f;
            float s = e0 + e1;
#pragma unroll
            for (int o = 16; o; o >>= 1) s += __shfl_xor_sync(0xffffffffu, s, o);
            float inv = 1.f / s;
            ab[OFF_P + n * 72 + lane]      = __float2bfloat16_rn(e0 * inv);
            ab[OFF_P + n * 72 + lane + 32] =
                (lane + 32 < N_) ? __float2bfloat16_rn(e1 * inv) : __nv_bfloat16(0.f);
        }
        __syncthreads();

        // ---- PV
        {
            float o[2][4];
#pragma unroll
            for (int i = 0; i < 2; i++)
#pragma unroll
                for (int q = 0; q < 4; q++) o[i][q] = 0.f;
            uint32_t vtb = smem_u32(ab + OFF_VT + h * VT_HEAD);
#pragma unroll
            for (int ks = 0; ks < 4; ks++) {
                uint32_t a[4];
                ldsm_x4(a, psb + (uint32_t)((wr * 16 + a_m) * 72 + ks * 16 + a_k) * 2);
#pragma unroll
                for (int ni = 0; ni < 2; ni++) {
                    uint32_t b[2];
                    ldsm_x2(b, vtb + (uint32_t)((wc * 16 + ni * 8 + lrow) * 72
                                                + ks * 16 + b_k) * 2);
                    mma_bf16(o[ni], a, b);
                }
            }
            __nv_bfloat16* ob = g_attno + (size_t)win * N_ * C_ + h * HD_;
#pragma unroll
            for (int ni = 0; ni < 2; ni++) {
#pragma unroll
                for (int half = 0; half < 2; half++) {
                    int row = wr * 16 + lr + half * 8;
                    if (row < N_) {
                        int col = wc * 16 + ni * 8 + 2 * lc;
                        *(__nv_bfloat162*)(ob + (size_t)row * C_ + col) =
                            __floats2bfloat162_rn(o[ni][half * 2], o[ni][half * 2 + 1]);
                    }
                }
            }
        }
        __syncthreads();
    }
}

// ----------------------------------------------------------------
extern "C" void kernel_launch(void* const* d_in, const int* in_sizes, int n_in,
                              void* d_out, int out_size)
{
    const float* x     = (const float*)d_in[0];
    const float* mask  = (const float*)d_in[1];
    const float* ln1g  = (const float*)d_in[2];
    const float* ln1b  = (const float*)d_in[3];
    const float* qkvw  = (const float*)d_in[4];
    const float* qkvb  = (const float*)d_in[5];
    const float* rpb   = (const float*)d_in[6];
    const float* projw = (const float*)d_in[7];
    const float* projb = (const float*)d_in[8];
    const float* ln2g  = (const float*)d_in[9];
    const float* ln2b  = (const float*)d_in[10];
    const float* fc1w  = (const float*)d_in[11];
    const float* fc1b  = (const float*)d_in[12];
    const float* fc2w  = (const float*)d_in[13];
    const float* fc2b  = (const float*)d_in[14];
    float* out = (float*)d_out;

    __nv_bfloat16 *hwin, *qkv, *attno, *ln2, *hid;
    __nv_bfloat16 *qkvwT, *projT, *fc1T, *fc2T;
    float *x1;
    cudaGetSymbolAddress((void**)&hwin,  g_hwin);
    cudaGetSymbolAddress((void**)&qkv,   g_qkv);
    cudaGetSymbolAddress((void**)&attno, g_attno);
    cudaGetSymbolAddress((void**)&x1,    g_x1);
    cudaGetSymbolAddress((void**)&ln2,   g_ln2);
    cudaGetSymbolAddress((void**)&hid,   g_hid);
    cudaGetSymbolAddress((void**)&qkvwT, g_qkvwT);
    cudaGetSymbolAddress((void**)&projT, g_projT);
    cudaGetSymbolAddress((void**)&fc1T,  g_fc1T);
    cudaGetSymbolAddress((void**)&fc2T,  g_fc2T);

    cudaFuncSetAttribute(gemm_mma<0>, cudaFuncAttributeMaxDynamicSharedMemorySize, SMEM_BYTES);
    cudaFuncSetAttribute(gemm_mma<1>, cudaFuncAttributeMaxDynamicSharedMemorySize, SMEM_BYTES);
    cudaFuncSetAttribute(gemm_mma<2>, cudaFuncAttributeMaxDynamicSharedMemorySize, SMEM_BYTES);
    cudaFuncSetAttribute(gemm_mma<3>, cudaFuncAttributeMaxDynamicSharedMemorySize, SMEM_BYTES);
    cudaFuncSetAttribute(attn_kernel, cudaFuncAttributeMaxDynamicSharedMemorySize, ATT_SMEM);

    // 0) merged weight convert + transpose
    wprep_all<<<432, dim3(32, 8)>>>(qkvw, projw, fc1w, fc2w,
                                    qkvwT, projT, fc1T, fc2T);

    const int ln_grid = TOK / 8;

    // 1) LN1 + shift + window partition -> bf16
    ln_kernel<1><<<ln_grid, 256>>>(x, hwin, ln1g, ln1b);

    // 2) QKV GEMM -> bf16
    gemm_mma<0><<<dim3(TOK / BM, C3 / BN), 256, SMEM_BYTES>>>(
        hwin, qkvwT, qkvb, nullptr, qkv, TOK, C3, C_);

    // 3) Windowed attention -> bf16
    attn_kernel<<<WINS, 256, ATT_SMEM>>>(rpb, mask);

    // 4) proj + window reverse + fp32 residual -> x1 (fp32)
    gemm_mma<1><<<dim3(TOK / BM, C_ / BN), 256, SMEM_BYTES>>>(
        attno, projT, projb, x, x1, TOK, C_, C_);

    // 5) LN2 -> bf16
    ln_kernel<0><<<ln_grid, 256>>>(x1, ln2, ln2g, ln2b);

    // 6) FC1 + GELU -> bf16
    gemm_mma<2><<<dim3(TOK / BM, HID_ / BN), 256, SMEM_BYTES>>>(
        ln2, fc1T, fc1b, nullptr, hid, TOK, HID_, C_);

    // 7) FC2 + fp32 residual -> out (fp32)
    gemm_mma<3><<<dim3(TOK / BM, C_ / BN), 256, SMEM_BYTES>>>(
        hid, fc2T, fc2b, x1, out, TOK, C_, HID_);
}

// round 15
// speedup vs baseline: 1.0403x; 1.0403x over previous
#include <cuda_runtime.h>
#include <cuda_bf16.h>
#include <cstdint>
#include <math.h>

// ---------------------------------------------------------------- constants
constexpr int B_   = 32;
constexpr int H_   = 56;
constexpr int W_   = 56;
constexpr int C_   = 192;
constexpr int NH_  = 6;
constexpr int WS_  = 7;
constexpr int SS_  = 3;
constexpr int N_   = 49;
constexpr int HD_  = 32;
constexpr int NWH  = 8;
constexpr int NW_  = 64;
constexpr int HID_ = 768;
constexpr int TOK  = B_ * H_ * W_;   // 100352
constexpr int WINS = B_ * NW_;       // 2048
constexpr int C3   = 3 * C_;         // 576

// GEMM tiling (mma.sync m16n8k16 bf16): 128x96 CTA, 64x24 warp tile, BK=64
constexpr int BM = 128;
constexpr int BN = 96;
constexpr int BK = 64;
constexpr int PITCH = 72;
constexpr int A_STAGE = BM * PITCH;
constexpr int B_STAGE = BN * PITCH;
constexpr int SMEM_BYTES = 2 * (A_STAGE + B_STAGE) * 2;   // 64512

// attention smem layout (bf16 units) — per-(window,head) blocks
constexpr int AQ_P = 40;             // q/k pitch (80B rows, stride 20 words)
constexpr int AP_P = 72;             // P / vT pitch (144B rows, stride 36 words)
constexpr int OFF_QS = 0;            // 64 x 40
constexpr int OFF_KX = 2560;         // 64 x 40
constexpr int OFF_VT = 5120;         // 32 x 72
constexpr int OFF_PS = 7424;         // 64 x 72
constexpr int ATT_BF16 = 12032;      // total bf16 units

// ---------------------------------------------------------------- scratch
__device__ __nv_bfloat16 g_hwin[(size_t)TOK * C_];
__device__ __nv_bfloat16 g_qkv[(size_t)TOK * C3];
__device__ __nv_bfloat16 g_attno[(size_t)TOK * C_];
__device__ float         g_x1[(size_t)TOK * C_];
__device__ __nv_bfloat16 g_ln2[(size_t)TOK * C_];
__device__ __nv_bfloat16 g_hid[(size_t)TOK * HID_];
__device__ __nv_bfloat16 g_qkvwT[(size_t)C3 * C_];
__device__ __nv_bfloat16 g_projT[(size_t)C_ * C_];
__device__ __nv_bfloat16 g_fc1T[(size_t)HID_ * C_];
__device__ __nv_bfloat16 g_fc2T[(size_t)C_ * HID_];

// ---------------------------------------------------------------- helpers
__device__ __forceinline__ uint32_t smem_u32(const void* p) {
    uint32_t a;
    asm("{ .reg .u64 t; cvta.to.shared.u64 t, %1; cvt.u32.u64 %0, t; }"
        : "=r"(a) : "l"(p));
    return a;
}
#define CP_ASYNC16(dst_u32, src_ptr) \
    asm volatile("cp.async.ca.shared.global [%0], [%1], 16;" \
        :: "r"(dst_u32), "l"(src_ptr) : "memory")
#define CP_ASYNC_COMMIT() asm volatile("cp.async.commit_group;" ::: "memory")
#define CP_ASYNC_WAIT_1() asm volatile("cp.async.wait_group 1;" ::: "memory")
#define CP_ASYNC_WAIT_0() asm volatile("cp.async.wait_group 0;" ::: "memory")

__device__ __forceinline__ void mma_bf16(
    float* d, const uint32_t* a, const uint32_t* b)
{
    asm volatile(
        "mma.sync.aligned.m16n8k16.row.col.f32.bf16.bf16.f32 "
        "{%0,%1,%2,%3}, {%4,%5,%6,%7}, {%8,%9}, {%0,%1,%2,%3};"
        : "+f"(d[0]), "+f"(d[1]), "+f"(d[2]), "+f"(d[3])
        : "r"(a[0]), "r"(a[1]), "r"(a[2]), "r"(a[3]),
          "r"(b[0]), "r"(b[1]));
}
__device__ __forceinline__ void ldsm_x4(uint32_t* r, uint32_t addr) {
    asm volatile("ldmatrix.sync.aligned.m8n8.x4.shared.b16 {%0,%1,%2,%3}, [%4];"
        : "=r"(r[0]), "=r"(r[1]), "=r"(r[2]), "=r"(r[3]) : "r"(addr));
}
__device__ __forceinline__ void ldsm_x2(uint32_t* r, uint32_t addr) {
    asm volatile("ldmatrix.sync.aligned.m8n8.x2.shared.b16 {%0,%1}, [%2];"
        : "=r"(r[0]), "=r"(r[1]) : "r"(addr));
}

// --------------------------------------------- merged weight prep (1 launch)
// fp32 [K][N] -> bf16 [N][K] for all 4 weights. 432 32x32 tiles total.
__global__ void wprep_all(
    const float* __restrict__ qkvw, const float* __restrict__ projw,
    const float* __restrict__ fc1w, const float* __restrict__ fc2w,
    __nv_bfloat16* __restrict__ qkvwT, __nv_bfloat16* __restrict__ projT,
    __nv_bfloat16* __restrict__ fc1T,  __nv_bfloat16* __restrict__ fc2T)
{
    __shared__ float t[32][33];
    int b = blockIdx.x;
    const float* src; __nv_bfloat16* dst; int K, N, t0;
    if (b < 108)      { src = qkvw; dst = qkvwT; K = 192; N = 576; t0 = b; }
    else if (b < 144) { src = projw; dst = projT; K = 192; N = 192; t0 = b - 108; }
    else if (b < 288) { src = fc1w; dst = fc1T; K = 192; N = 768; t0 = b - 144; }
    else              { src = fc2w; dst = fc2T; K = 768; N = 192; t0 = b - 288; }
    int ntiles = N / 32;
    int kb = (t0 / ntiles) * 32, nb = (t0 % ntiles) * 32;
    int x = threadIdx.x, y = threadIdx.y;      // 32 x 8
    for (int i = y; i < 32; i += 8)
        t[i][x] = src[(size_t)(kb + i) * N + nb + x];
    __syncthreads();
    for (int i = y; i < 32; i += 8)
        dst[(size_t)(nb + i) * K + kb + x] = __float2bfloat16_rn(t[x][i]);
}

// ---------------------------------------------------------------- LayerNorm
template <int PART>
__global__ void __launch_bounds__(256) ln_kernel(
    const float* __restrict__ src, __nv_bfloat16* __restrict__ dst,
    const float* __restrict__ gamma, const float* __restrict__ beta)
{
    int warp = threadIdx.x >> 5;
    int lane = threadIdx.x & 31;
    int t = blockIdx.x * 8 + warp;
    if (t >= TOK) return;

    const float* xr = src + (size_t)t * C_;
    float v[6];
    float s = 0.f;
#pragma unroll
    for (int i = 0; i < 6; i++) { v[i] = xr[lane + 32 * i]; s += v[i]; }
#pragma unroll
    for (int o = 16; o; o >>= 1) s += __shfl_xor_sync(0xffffffffu, s, o);
    float mean = s * (1.f / 192.f);
    float ss = 0.f;
#pragma unroll
    for (int i = 0; i < 6; i++) { float d = v[i] - mean; ss += d * d; }
#pragma unroll
    for (int o = 16; o; o >>= 1) ss += __shfl_xor_sync(0xffffffffu, ss, o);
    float rstd = rsqrtf(ss * (1.f / 192.f) + 1e-5f);

    int dt = t;
    if (PART) {
        int bb = t / (H_ * W_);
        int rem = t - bb * (H_ * W_);
        int h = rem / W_, w = rem - (rem / W_) * W_;
        int hs = h - SS_; if (hs < 0) hs += H_;
        int ws = w - SS_; if (ws < 0) ws += W_;
        int wl = (hs / WS_) * NWH + (ws / WS_);
        int n  = (hs % WS_) * WS_ + (ws % WS_);
        dt = bb * (NW_ * N_) + wl * N_ + n;
    }
    __nv_bfloat16* o = dst + (size_t)dt * C_;
#pragma unroll
    for (int i = 0; i < 6; i++) {
        int c = lane + 32 * i;
        o[c] = __float2bfloat16_rn((v[i] - mean) * rstd * gamma[c] + beta[c]);
    }
}

// ---------------------------------------------------------------- bf16 GEMM
template <int EPI>
__global__ void __launch_bounds__(256) gemm_mma(
    const __nv_bfloat16* __restrict__ A, const __nv_bfloat16* __restrict__ Bt,
    const float* __restrict__ bias, const float* __restrict__ add,
    void* __restrict__ Cout, int M, int N, int K)
{
    extern __shared__ __align__(16) __nv_bfloat16 smem[];
    __nv_bfloat16* Asm = smem;
    __nv_bfloat16* Bsm = smem + 2 * A_STAGE;

    const int tid  = threadIdx.x;
    const int wid  = tid >> 5;
    const int lane = tid & 31;
    const int wm   = wid >> 2;
    const int wn   = wid & 3;
    const int lr   = lane >> 2;
    const int lc   = lane & 3;
    const int bm   = blockIdx.x * BM;
    const int bn   = blockIdx.y * BN;
    const int nk   = K / BK;

    const int lj   = lane >> 3;
    const int lrow = lane & 7;
    const int a_m  = (lj & 1) * 8 + lrow;
    const int a_k  = (lj >> 1) * 8;
    const int b_k  = (lj & 1) * 8;

    float acc[4][3][4];
#pragma unroll
    for (int i = 0; i < 4; i++)
#pragma unroll
        for (int j = 0; j < 3; j++)
#pragma unroll
            for (int q = 0; q < 4; q++) acc[i][j][q] = 0.f;

    uint32_t asb = smem_u32(Asm);
    uint32_t bsb = smem_u32(Bsm);

    auto load_tile = [&](int k0, int st) {
#pragma unroll
        for (int i = tid; i < 1024; i += 256) {
            int m   = i >> 3;
            int k16 = i & 7;
            const __nv_bfloat16* src = A + (size_t)(bm + m) * K + k0 * BK + k16 * 8;
            uint32_t dst = asb + (uint32_t)(st * A_STAGE + m * PITCH + k16 * 8) * 2;
            CP_ASYNC16(dst, src);
        }
#pragma unroll
        for (int i = tid; i < 768; i += 256) {
            int n   = i >> 3;
            int k16 = i & 7;
            const __nv_bfloat16* src = Bt + (size_t)(bn + n) * K + k0 * BK + k16 * 8;
            uint32_t dst = bsb + (uint32_t)(st * B_STAGE + n * PITCH + k16 * 8) * 2;
            CP_ASYNC16(dst, src);
        }
        CP_ASYNC_COMMIT();
    };

    load_tile(0, 0);

    for (int k0 = 0; k0 < nk; k0++) {
        if (k0 + 1 < nk) { load_tile(k0 + 1, (k0 + 1) & 1); CP_ASYNC_WAIT_1(); }
        else             { CP_ASYNC_WAIT_0(); }
        __syncthreads();

        uint32_t asb_st = asb + (uint32_t)((k0 & 1) * A_STAGE) * 2;
        uint32_t bsb_st = bsb + (uint32_t)((k0 & 1) * B_STAGE) * 2;
#pragma unroll
        for (int ks = 0; ks < 4; ks++) {
            uint32_t a[4][4];
#pragma unroll
            for (int mi = 0; mi < 4; mi++) {
                uint32_t addr = asb_st +
                    (uint32_t)((wm * 64 + mi * 16 + a_m) * PITCH + ks * 16 + a_k) * 2;
                ldsm_x4(a[mi], addr);
            }
            uint32_t b[3][2];
#pragma unroll
            for (int ni = 0; ni < 3; ni++) {
                uint32_t addr = bsb_st +
                    (uint32_t)((wn * 24 + ni * 8 + lrow) * PITCH + ks * 16 + b_k) * 2;
                ldsm_x2(b[ni], addr);
            }
#pragma unroll
            for (int mi = 0; mi < 4; mi++)
#pragma unroll
                for (int ni = 0; ni < 3; ni++)
                    mma_bf16(acc[mi][ni], a[mi], b[ni]);
        }
        __syncthreads();
    }

#pragma unroll
    for (int mi = 0; mi < 4; mi++) {
#pragma unroll
        for (int half = 0; half < 2; half++) {
            int row = bm + wm * 64 + mi * 16 + lr + half * 8;
            int orow = row;
            if (EPI == 1) {
                int win = row / N_, n = row - win * N_;
                int b = win >> 6, wl = win & 63;
                int hs = (wl >> 3) * WS_ + n / WS_;
                int ws = (wl & 7) * WS_ + (n - (n / WS_) * WS_);
                int h = hs + SS_; if (h >= H_) h -= H_;
                int w = ws + SS_; if (w >= W_) w -= W_;
                orow = (b * H_ + h) * W_ + w;
            }
#pragma unroll
            for (int ni = 0; ni < 3; ni++) {
                int c = bn + wn * 24 + ni * 8 + 2 * lc;
                float2 bv = *(const float2*)(bias + c);
                float vx = acc[mi][ni][half * 2 + 0] + bv.x;
                float vy = acc[mi][ni][half * 2 + 1] + bv.y;
                if (EPI == 1) {
                    float2 av = *(const float2*)(add + (size_t)orow * N + c);
                    vx += av.x; vy += av.y;
                }
                if (EPI == 2) { vx *= normcdff(vx); vy *= normcdff(vy); }
                if (EPI == 3) {
                    float2 av = *(const float2*)(add + (size_t)row * N + c);
                    vx += av.x; vy += av.y;
                }
                if (EPI == 0 || EPI == 2) {
                    __nv_bfloat16* Co = (__nv_bfloat16*)Cout;
                    *(__nv_bfloat162*)(Co + (size_t)orow * N + c) =
                        __floats2bfloat162_rn(vx, vy);
                } else {
                    float* Co = (float*)Cout;
                    *(float2*)(Co + (size_t)orow * N + c) = make_float2(vx, vy);
                }
            }
        }
    }
}

// ---------------------------------------------------------------- attention
// One block per (window, head), 128 threads = 4 warps.  Both matmuls on
// bf16 mma.sync (padded 49->64).  Scores staged fp32; softmax applies
// scale + RPB + mask at read time; P rounded to bf16 for the PV MMA.
__global__ void __launch_bounds__(128) attn_kernel(
    const float* __restrict__ rpb, const float* __restrict__ mask)
{
    int win  = blockIdx.x;
    int head = blockIdx.y;
    int tid  = threadIdx.x;
    int warp = tid >> 5;
    int lane = tid & 31;

    __shared__ __align__(16) __nv_bfloat16 ab[ATT_BF16];
    __shared__ __align__(16) float sc[64][52];
    __shared__ __align__(16) float rpbs[169];

    // zero the bf16 arena (padding rows/cols must be 0)
    uint32_t* abw = (uint32_t*)ab;
    for (int i = tid; i < ATT_BF16 / 2; i += 128) abw[i] = 0u;

    const __nv_bfloat16* base = g_qkv + (size_t)win * N_ * C3 + head * HD_;
    for (int idx = tid; idx < 169; idx += 128)
        rpbs[idx] = rpb[idx * NH_ + head];
    __syncthreads();

    // load q, k, vT (raw bf16 copies; scale folded into softmax)
    for (int idx = tid; idx < N_ * HD_; idx += 128) {
        int n = idx >> 5, d = idx & 31;
        const __nv_bfloat16* row = base + (size_t)n * C3 + d;
        ab[OFF_QS + n * AQ_P + d] = row[0];
        ab[OFF_KX + n * AQ_P + d] = row[C_];
        ab[OFF_VT + d * AP_P + n] = row[2 * C_];
    }
    __syncthreads();

    const int lj   = lane >> 3;
    const int lrow = lane & 7;
    const int a_m  = (lj & 1) * 8 + lrow;
    const int a_k  = (lj >> 1) * 8;
    const int b_k  = (lj & 1) * 8;
    const int lr   = lane >> 2;
    const int lc   = lane & 3;

    uint32_t qsb = smem_u32(ab + OFF_QS);
    uint32_t kxb = smem_u32(ab + OFF_KX);
    uint32_t vtb = smem_u32(ab + OFF_VT);
    uint32_t psb = smem_u32(ab + OFF_PS);

    // ---- QK^T: each warp computes rows [warp*16, warp*16+16) x 64 cols
    {
        float c[8][4];
#pragma unroll
        for (int i = 0; i < 8; i++)
#pragma unroll
            for (int q = 0; q < 4; q++) c[i][q] = 0.f;
#pragma unroll
        for (int ks = 0; ks < 2; ks++) {
            uint32_t a[4];
            ldsm_x4(a, qsb + (uint32_t)((warp * 16 + a_m) * AQ_P + ks * 16 + a_k) * 2);
#pragma unroll
            for (int ni = 0; ni < 8; ni++) {
                uint32_t b[2];
                ldsm_x2(b, kxb + (uint32_t)((ni * 8 + lrow) * AQ_P + ks * 16 + b_k) * 2);
                mma_bf16(c[ni], a, b);
            }
        }
#pragma unroll
        for (int ni = 0; ni < 8; ni++) {
            sc[warp * 16 + lr][ni * 8 + 2 * lc]         = c[ni][0];
            sc[warp * 16 + lr][ni * 8 + 2 * lc + 1]     = c[ni][1];
            sc[warp * 16 + lr + 8][ni * 8 + 2 * lc]     = c[ni][2];
            sc[warp * 16 + lr + 8][ni * 8 + 2 * lc + 1] = c[ni][3];
        }
    }
    __syncthreads();

    // ---- softmax rows (scale + bias + mask applied here); write P as bf16
    const float scale = 0.17677669529663687f;
    const float* mrow = mask + (size_t)(win & (NW_ - 1)) * N_ * N_;
    for (int n = warp; n < N_; n += 4) {
        int i1 = n / WS_, j1 = n - (n / WS_) * WS_;
        float v0 = -1e30f, v1 = -1e30f;
        if (lane < N_) {
            int m = lane;
            int i2 = m / WS_, j2 = m - i2 * WS_;
            int rel = (i1 - i2 + WS_ - 1) * (2 * WS_ - 1) + (j1 - j2 + WS_ - 1);
            v0 = sc[n][m] * scale + rpbs[rel] + mrow[n * N_ + m];
        }
        if (lane + 32 < N_) {
            int m = lane + 32;
            int i2 = m / WS_, j2 = m - i2 * WS_;
            int rel = (i1 - i2 + WS_ - 1) * (2 * WS_ - 1) + (j1 - j2 + WS_ - 1);
            v1 = sc[n][m] * scale + rpbs[rel] + mrow[n * N_ + m];
        }
        float mx = fmaxf(v0, v1);
#pragma unroll
        for (int o = 16; o; o >>= 1) mx = fmaxf(mx, __shfl_xor_sync(0xffffffffu, mx, o));
        float e0 = (lane < N_)      ? __expf(v0 - mx) : 0.f;
        float e1 = (lane + 32 < N_) ? __expf(v1 - mx) : 0.f;
        float s = e0 + e1;
#pragma unroll
        for (int o = 16; o; o >>= 1) s += __shfl_xor_sync(0xffffffffu, s, o);
        float inv = 1.f / s;
        if (lane < N_)
            ab[OFF_PS + n * AP_P + lane]      = __float2bfloat16_rn(e0 * inv);
        if (lane + 32 < N_)
            ab[OFF_PS + n * AP_P + lane + 32] = __float2bfloat16_rn(e1 * inv);
    }
    __syncthreads();

    // ---- PV: rows [warp*16, +16) x 32 d-cols, K = 64 (padded keys are 0)
    {
        float o[4][4];
#pragma unroll
        for (int i = 0; i < 4; i++)
#pragma unroll
            for (int q = 0; q < 4; q++) o[i][q] = 0.f;
#pragma unroll
        for (int ks = 0; ks < 4; ks++) {
            uint32_t a[4];
            ldsm_x4(a, psb + (uint32_t)((warp * 16 + a_m) * AP_P + ks * 16 + a_k) * 2);
#pragma unroll
            for (int ni = 0; ni < 4; ni++) {
                uint32_t b[2];
                ldsm_x2(b, vtb + (uint32_t)((ni * 8 + lrow) * AP_P + ks * 16 + b_k) * 2);
                mma_bf16(o[ni], a, b);
            }
        }
        __nv_bfloat16* ob = g_attno + (size_t)win * N_ * C_ + head * HD_;
#pragma unroll
        for (int ni = 0; ni < 4; ni++) {
#pragma unroll
            for (int half = 0; half < 2; half++) {
                int row = warp * 16 + lr + half * 8;
                if (row < N_) {
                    int col = ni * 8 + 2 * lc;
                    *(__nv_bfloat162*)(ob + (size_t)row * C_ + col) =
                        __floats2bfloat162_rn(o[ni][half * 2], o[ni][half * 2 + 1]);
                }
            }
        }
    }
}

// ----------------------------------------------------------------
extern "C" void kernel_launch(void* const* d_in, const int* in_sizes, int n_in,
                              void* d_out, int out_size)
{
    const float* x     = (const float*)d_in[0];
    const float* mask  = (const float*)d_in[1];
    const float* ln1g  = (const float*)d_in[2];
    const float* ln1b  = (const float*)d_in[3];
    const float* qkvw  = (const float*)d_in[4];
    const float* qkvb  = (const float*)d_in[5];
    const float* rpb   = (const float*)d_in[6];
    const float* projw = (const float*)d_in[7];
    const float* projb = (const float*)d_in[8];
    const float* ln2g  = (const float*)d_in[9];
    const float* ln2b  = (const float*)d_in[10];
    const float* fc1w  = (const float*)d_in[11];
    const float* fc1b  = (const float*)d_in[12];
    const float* fc2w  = (const float*)d_in[13];
    const float* fc2b  = (const float*)d_in[14];
    float* out = (float*)d_out;

    __nv_bfloat16 *hwin, *qkv, *attno, *ln2, *hid;
    __nv_bfloat16 *qkvwT, *projT, *fc1T, *fc2T;
    float *x1;
    cudaGetSymbolAddress((void**)&hwin,  g_hwin);
    cudaGetSymbolAddress((void**)&qkv,   g_qkv);
    cudaGetSymbolAddress((void**)&attno, g_attno);
    cudaGetSymbolAddress((void**)&x1,    g_x1);
    cudaGetSymbolAddress((void**)&ln2,   g_ln2);
    cudaGetSymbolAddress((void**)&hid,   g_hid);
    cudaGetSymbolAddress((void**)&qkvwT, g_qkvwT);
    cudaGetSymbolAddress((void**)&projT, g_projT);
    cudaGetSymbolAddress((void**)&fc1T,  g_fc1T);
    cudaGetSymbolAddress((void**)&fc2T,  g_fc2T);

    cudaFuncSetAttribute(gemm_mma<0>, cudaFuncAttributeMaxDynamicSharedMemorySize, SMEM_BYTES);
    cudaFuncSetAttribute(gemm_mma<1>, cudaFuncAttributeMaxDynamicSharedMemorySize, SMEM_BYTES);
    cudaFuncSetAttribute(gemm_mma<2>, cudaFuncAttributeMaxDynamicSharedMemorySize, SMEM_BYTES);
    cudaFuncSetAttribute(gemm_mma<3>, cudaFuncAttributeMaxDynamicSharedMemorySize, SMEM_BYTES);

    // 0) merged weight convert + transpose (1 launch, 432 tiles)
    wprep_all<<<432, dim3(32, 8)>>>(qkvw, projw, fc1w, fc2w,
                                    qkvwT, projT, fc1T, fc2T);

    const int ln_grid = TOK / 8;

    // 1) LN1 + shift + window partition -> bf16
    ln_kernel<1><<<ln_grid, 256>>>(x, hwin, ln1g, ln1b);

    // 2) QKV GEMM -> bf16
    gemm_mma<0><<<dim3(TOK / BM, C3 / BN), 256, SMEM_BYTES>>>(
        hwin, qkvwT, qkvb, nullptr, qkv, TOK, C3, C_);

    // 3) Windowed attention (tensor-core, per (win,head)) -> bf16
    attn_kernel<<<dim3(WINS, NH_), 128>>>(rpb, mask);

    // 4) proj + window reverse + fp32 residual -> x1 (fp32)
    gemm_mma<1><<<dim3(TOK / BM, C_ / BN), 256, SMEM_BYTES>>>(
        attno, projT, projb, x, x1, TOK, C_, C_);

    // 5) LN2 -> bf16
    ln_kernel<0><<<ln_grid, 256>>>(x1, ln2, ln2g, ln2b);

    // 6) FC1 + GELU -> bf16
    gemm_mma<2><<<dim3(TOK / BM, HID_ / BN), 256, SMEM_BYTES>>>(
        ln2, fc1T, fc1b, nullptr, hid, TOK, HID_, C_);

    // 7) FC2 + fp32 residual -> out (fp32)
    gemm_mma<3><<<dim3(TOK / BM, C_ / BN), 256, SMEM_BYTES>>>(
        hid, fc2T, fc2b, x1, out, TOK, C_, HID_);
}

// round 16
// speedup vs baseline: 1.2199x; 1.1727x over previous
#include <cuda_runtime.h>
#include <cuda_bf16.h>
#include <cstdint>
#include <math.h>

// ---------------------------------------------------------------- constants
constexpr int B_   = 32;
constexpr int H_   = 56;
constexpr int W_   = 56;
constexpr int C_   = 192;
constexpr int NH_  = 6;
constexpr int WS_  = 7;
constexpr int SS_  = 3;
constexpr int N_   = 49;
constexpr int HD_  = 32;
constexpr int NWH  = 8;
constexpr int NW_  = 64;
constexpr int HID_ = 768;
constexpr int TOK  = B_ * H_ * W_;   // 100352
constexpr int WINS = B_ * NW_;       // 2048
constexpr int C3   = 3 * C_;         // 576

// GEMM tiling (mma.sync m16n8k16 bf16): 128x96 CTA, 64x24 warp tile, BK=64
constexpr int BM = 128;
constexpr int BN = 96;
constexpr int BK = 64;
constexpr int PITCH = 72;
constexpr int A_STAGE = BM * PITCH;
constexpr int B_STAGE = BN * PITCH;
constexpr int SMEM_BYTES = 2 * (A_STAGE + B_STAGE) * 2;   // 64512

// attention smem layout (bf16 units) — per-(window,head) blocks
constexpr int AQ_P = 40;             // q/k pitch (80B rows, stride 20 words)
constexpr int AP_P = 72;             // vT pitch (144B rows, stride 36 words)
constexpr int OFF_QS = 0;            // 64 x 40
constexpr int OFF_KX = 2560;         // 64 x 40
constexpr int OFF_VT = 5120;         // 32 x 72
constexpr int ATT_BF16 = 7424;       // total bf16 units (no P/score arrays)

// ---------------------------------------------------------------- scratch
__device__ __nv_bfloat16 g_hwin[(size_t)TOK * C_];
__device__ __nv_bfloat16 g_qkv[(size_t)TOK * C3];
__device__ __nv_bfloat16 g_attno[(size_t)TOK * C_];
__device__ float         g_x1[(size_t)TOK * C_];
__device__ __nv_bfloat16 g_ln2[(size_t)TOK * C_];
__device__ __nv_bfloat16 g_hid[(size_t)TOK * HID_];
__device__ __nv_bfloat16 g_qkvwT[(size_t)C3 * C_];
__device__ __nv_bfloat16 g_projT[(size_t)C_ * C_];
__device__ __nv_bfloat16 g_fc1T[(size_t)HID_ * C_];
__device__ __nv_bfloat16 g_fc2T[(size_t)C_ * HID_];

// ---------------------------------------------------------------- helpers
__device__ __forceinline__ uint32_t smem_u32(const void* p) {
    uint32_t a;
    asm("{ .reg .u64 t; cvta.to.shared.u64 t, %1; cvt.u32.u64 %0, t; }"
        : "=r"(a) : "l"(p));
    return a;
}
#define CP_ASYNC16(dst_u32, src_ptr) \
    asm volatile("cp.async.ca.shared.global [%0], [%1], 16;" \
        :: "r"(dst_u32), "l"(src_ptr) : "memory")
#define CP_ASYNC_COMMIT() asm volatile("cp.async.commit_group;" ::: "memory")
#define CP_ASYNC_WAIT_1() asm volatile("cp.async.wait_group 1;" ::: "memory")
#define CP_ASYNC_WAIT_0() asm volatile("cp.async.wait_group 0;" ::: "memory")

__device__ __forceinline__ void mma_bf16(
    float* d, const uint32_t* a, const uint32_t* b)
{
    asm volatile(
        "mma.sync.aligned.m16n8k16.row.col.f32.bf16.bf16.f32 "
        "{%0,%1,%2,%3}, {%4,%5,%6,%7}, {%8,%9}, {%0,%1,%2,%3};"
        : "+f"(d[0]), "+f"(d[1]), "+f"(d[2]), "+f"(d[3])
        : "r"(a[0]), "r"(a[1]), "r"(a[2]), "r"(a[3]),
          "r"(b[0]), "r"(b[1]));
}
__device__ __forceinline__ void ldsm_x4(uint32_t* r, uint32_t addr) {
    asm volatile("ldmatrix.sync.aligned.m8n8.x4.shared.b16 {%0,%1,%2,%3}, [%4];"
        : "=r"(r[0]), "=r"(r[1]), "=r"(r[2]), "=r"(r[3]) : "r"(addr));
}
__device__ __forceinline__ void ldsm_x2(uint32_t* r, uint32_t addr) {
    asm volatile("ldmatrix.sync.aligned.m8n8.x2.shared.b16 {%0,%1}, [%2];"
        : "=r"(r[0]), "=r"(r[1]) : "r"(addr));
}
__device__ __forceinline__ uint32_t packbf(float x, float y) {
    __nv_bfloat162 t = __floats2bfloat162_rn(x, y);
    return *(uint32_t*)&t;
}

// --------------------------------------------- merged weight prep (1 launch)
__global__ void wprep_all(
    const float* __restrict__ qkvw, const float* __restrict__ projw,
    const float* __restrict__ fc1w, const float* __restrict__ fc2w,
    __nv_bfloat16* __restrict__ qkvwT, __nv_bfloat16* __restrict__ projT,
    __nv_bfloat16* __restrict__ fc1T,  __nv_bfloat16* __restrict__ fc2T)
{
    __shared__ float t[32][33];
    int b = blockIdx.x;
    const float* src; __nv_bfloat16* dst; int K, N, t0;
    if (b < 108)      { src = qkvw; dst = qkvwT; K = 192; N = 576; t0 = b; }
    else if (b < 144) { src = projw; dst = projT; K = 192; N = 192; t0 = b - 108; }
    else if (b < 288) { src = fc1w; dst = fc1T; K = 192; N = 768; t0 = b - 144; }
    else              { src = fc2w; dst = fc2T; K = 768; N = 192; t0 = b - 288; }
    int ntiles = N / 32;
    int kb = (t0 / ntiles) * 32, nb = (t0 % ntiles) * 32;
    int x = threadIdx.x, y = threadIdx.y;      // 32 x 8
    for (int i = y; i < 32; i += 8)
        t[i][x] = src[(size_t)(kb + i) * N + nb + x];
    __syncthreads();
    for (int i = y; i < 32; i += 8)
        dst[(size_t)(nb + i) * K + kb + x] = __float2bfloat16_rn(t[x][i]);
}

// ---------------------------------------------------------------- LayerNorm
template <int PART>
__global__ void __launch_bounds__(256) ln_kernel(
    const float* __restrict__ src, __nv_bfloat16* __restrict__ dst,
    const float* __restrict__ gamma, const float* __restrict__ beta)
{
    int warp = threadIdx.x >> 5;
    int lane = threadIdx.x & 31;
    int t = blockIdx.x * 8 + warp;
    if (t >= TOK) return;

    const float* xr = src + (size_t)t * C_;
    float v[6];
    float s = 0.f;
#pragma unroll
    for (int i = 0; i < 6; i++) { v[i] = xr[lane + 32 * i]; s += v[i]; }
#pragma unroll
    for (int o = 16; o; o >>= 1) s += __shfl_xor_sync(0xffffffffu, s, o);
    float mean = s * (1.f / 192.f);
    float ss = 0.f;
#pragma unroll
    for (int i = 0; i < 6; i++) { float d = v[i] - mean; ss += d * d; }
#pragma unroll
    for (int o = 16; o; o >>= 1) ss += __shfl_xor_sync(0xffffffffu, ss, o);
    float rstd = rsqrtf(ss * (1.f / 192.f) + 1e-5f);

    int dt = t;
    if (PART) {
        int bb = t / (H_ * W_);
        int rem = t - bb * (H_ * W_);
        int h = rem / W_, w = rem - (rem / W_) * W_;
        int hs = h - SS_; if (hs < 0) hs += H_;
        int ws = w - SS_; if (ws < 0) ws += W_;
        int wl = (hs / WS_) * NWH + (ws / WS_);
        int n  = (hs % WS_) * WS_ + (ws % WS_);
        dt = bb * (NW_ * N_) + wl * N_ + n;
    }
    __nv_bfloat16* o = dst + (size_t)dt * C_;
#pragma unroll
    for (int i = 0; i < 6; i++) {
        int c = lane + 32 * i;
        o[c] = __float2bfloat16_rn((v[i] - mean) * rstd * gamma[c] + beta[c]);
    }
}

// ---------------------------------------------------------------- bf16 GEMM
template <int EPI>
__global__ void __launch_bounds__(256) gemm_mma(
    const __nv_bfloat16* __restrict__ A, const __nv_bfloat16* __restrict__ Bt,
    const float* __restrict__ bias, const float* __restrict__ add,
    void* __restrict__ Cout, int M, int N, int K)
{
    extern __shared__ __align__(16) __nv_bfloat16 smem[];
    __nv_bfloat16* Asm = smem;
    __nv_bfloat16* Bsm = smem + 2 * A_STAGE;

    const int tid  = threadIdx.x;
    const int wid  = tid >> 5;
    const int lane = tid & 31;
    const int wm   = wid >> 2;
    const int wn   = wid & 3;
    const int lr   = lane >> 2;
    const int lc   = lane & 3;
    const int bm   = blockIdx.x * BM;
    const int bn   = blockIdx.y * BN;
    const int nk   = K / BK;

    const int lj   = lane >> 3;
    const int lrow = lane & 7;
    const int a_m  = (lj & 1) * 8 + lrow;
    const int a_k  = (lj >> 1) * 8;
    const int b_k  = (lj & 1) * 8;

    float acc[4][3][4];
#pragma unroll
    for (int i = 0; i < 4; i++)
#pragma unroll
        for (int j = 0; j < 3; j++)
#pragma unroll
            for (int q = 0; q < 4; q++) acc[i][j][q] = 0.f;

    uint32_t asb = smem_u32(Asm);
    uint32_t bsb = smem_u32(Bsm);

    auto load_tile = [&](int k0, int st) {
#pragma unroll
        for (int i = tid; i < 1024; i += 256) {
            int m   = i >> 3;
            int k16 = i & 7;
            const __nv_bfloat16* src = A + (size_t)(bm + m) * K + k0 * BK + k16 * 8;
            uint32_t dst = asb + (uint32_t)(st * A_STAGE + m * PITCH + k16 * 8) * 2;
            CP_ASYNC16(dst, src);
        }
#pragma unroll
        for (int i = tid; i < 768; i += 256) {
            int n   = i >> 3;
            int k16 = i & 7;
            const __nv_bfloat16* src = Bt + (size_t)(bn + n) * K + k0 * BK + k16 * 8;
            uint32_t dst = bsb + (uint32_t)(st * B_STAGE + n * PITCH + k16 * 8) * 2;
            CP_ASYNC16(dst, src);
        }
        CP_ASYNC_COMMIT();
    };

    load_tile(0, 0);

    for (int k0 = 0; k0 < nk; k0++) {
        if (k0 + 1 < nk) { load_tile(k0 + 1, (k0 + 1) & 1); CP_ASYNC_WAIT_1(); }
        else             { CP_ASYNC_WAIT_0(); }
        __syncthreads();

        uint32_t asb_st = asb + (uint32_t)((k0 & 1) * A_STAGE) * 2;
        uint32_t bsb_st = bsb + (uint32_t)((k0 & 1) * B_STAGE) * 2;
#pragma unroll
        for (int ks = 0; ks < 4; ks++) {
            uint32_t a[4][4];
#pragma unroll
            for (int mi = 0; mi < 4; mi++) {
                uint32_t addr = asb_st +
                    (uint32_t)((wm * 64 + mi * 16 + a_m) * PITCH + ks * 16 + a_k) * 2;
                ldsm_x4(a[mi], addr);
            }
            uint32_t b[3][2];
#pragma unroll
            for (int ni = 0; ni < 3; ni++) {
                uint32_t addr = bsb_st +
                    (uint32_t)((wn * 24 + ni * 8 + lrow) * PITCH + ks * 16 + b_k) * 2;
                ldsm_x2(b[ni], addr);
            }
#pragma unroll
            for (int mi = 0; mi < 4; mi++)
#pragma unroll
                for (int ni = 0; ni < 3; ni++)
                    mma_bf16(acc[mi][ni], a[mi], b[ni]);
        }
        __syncthreads();
    }

#pragma unroll
    for (int mi = 0; mi < 4; mi++) {
#pragma unroll
        for (int half = 0; half < 2; half++) {
            int row = bm + wm * 64 + mi * 16 + lr + half * 8;
            int orow = row;
            if (EPI == 1) {
                int win = row / N_, n = row - win * N_;
                int b = win >> 6, wl = win & 63;
                int hs = (wl >> 3) * WS_ + n / WS_;
                int ws = (wl & 7) * WS_ + (n - (n / WS_) * WS_);
                int h = hs + SS_; if (h >= H_) h -= H_;
                int w = ws + SS_; if (w >= W_) w -= W_;
                orow = (b * H_ + h) * W_ + w;
            }
#pragma unroll
            for (int ni = 0; ni < 3; ni++) {
                int c = bn + wn * 24 + ni * 8 + 2 * lc;
                float2 bv = *(const float2*)(bias + c);
                float vx = acc[mi][ni][half * 2 + 0] + bv.x;
                float vy = acc[mi][ni][half * 2 + 1] + bv.y;
                if (EPI == 1) {
                    float2 av = *(const float2*)(add + (size_t)orow * N + c);
                    vx += av.x; vy += av.y;
                }
                if (EPI == 2) { vx *= normcdff(vx); vy *= normcdff(vy); }
                if (EPI == 3) {
                    float2 av = *(const float2*)(add + (size_t)row * N + c);
                    vx += av.x; vy += av.y;
                }
                if (EPI == 0 || EPI == 2) {
                    __nv_bfloat16* Co = (__nv_bfloat16*)Cout;
                    *(__nv_bfloat162*)(Co + (size_t)orow * N + c) =
                        __floats2bfloat162_rn(vx, vy);
                } else {
                    float* Co = (float*)Cout;
                    *(float2*)(Co + (size_t)orow * N + c) = make_float2(vx, vy);
                }
            }
        }
    }
}

// ---------------------------------------------------------------- attention
// One block per (window, head), 128 threads = 4 warps.  R15 shell (same
// staging + full arena zero), but each warp now softmaxes ITS OWN rows in
// registers (accumulator frag == A-operand frag) and feeds PV directly:
// only ONE barrier, no score/P smem.
__global__ void __launch_bounds__(128) attn_kernel(
    const float* __restrict__ rpb, const float* __restrict__ mask)
{
    int win  = blockIdx.x;
    int head = blockIdx.y;
    int tid  = threadIdx.x;
    int warp = tid >> 5;
    int lane = tid & 31;

    __shared__ __align__(16) __nv_bfloat16 ab[ATT_BF16];
    __shared__ __align__(16) float rpbs[169];

    // zero the bf16 arena (padding rows/cols must be 0)
    uint32_t* abw = (uint32_t*)ab;
    for (int i = tid; i < ATT_BF16 / 2; i += 128) abw[i] = 0u;

    const __nv_bfloat16* base = g_qkv + (size_t)win * N_ * C3 + head * HD_;
    for (int idx = tid; idx < 169; idx += 128)
        rpbs[idx] = rpb[idx * NH_ + head];
    __syncthreads();

    // load q, k, vT (raw bf16 copies; scale folded into softmax)
    for (int idx = tid; idx < N_ * HD_; idx += 128) {
        int n = idx >> 5, d = idx & 31;
        const __nv_bfloat16* row = base + (size_t)n * C3 + d;
        ab[OFF_QS + n * AQ_P + d] = row[0];
        ab[OFF_KX + n * AQ_P + d] = row[C_];
        ab[OFF_VT + d * AP_P + n] = row[2 * C_];
    }
    __syncthreads();

    const int lj   = lane >> 3;
    const int lrow = lane & 7;
    const int a_m  = (lj & 1) * 8 + lrow;
    const int a_k  = (lj >> 1) * 8;
    const int b_k  = (lj & 1) * 8;
    const int lr   = lane >> 2;
    const int lc   = lane & 3;

    uint32_t qsb = smem_u32(ab + OFF_QS);
    uint32_t kxb = smem_u32(ab + OFF_KX);
    uint32_t vtb = smem_u32(ab + OFF_VT);

    const float scale = 0.17677669529663687f;
    const float* mrow = mask + (size_t)(win & (NW_ - 1)) * N_ * N_;

    // ---- QK^T: warp computes rows [warp*16, +16) x 64 cols
    float c[8][4];
#pragma unroll
    for (int i = 0; i < 8; i++)
#pragma unroll
        for (int q = 0; q < 4; q++) c[i][q] = 0.f;
#pragma unroll
    for (int ks = 0; ks < 2; ks++) {
        uint32_t a[4];
        ldsm_x4(a, qsb + (uint32_t)((warp * 16 + a_m) * AQ_P + ks * 16 + a_k) * 2);
#pragma unroll
        for (int ni = 0; ni < 8; ni++) {
            uint32_t b[2];
            ldsm_x2(b, kxb + (uint32_t)((ni * 8 + lrow) * AQ_P + ks * 16 + b_k) * 2);
            mma_bf16(c[ni], a, b);
        }
    }

    // ---- bias + guards (rows n0/n1, cols per ni); pads -> -1e30
    int n0 = warp * 16 + lr, n1 = n0 + 8;
    bool r0v = n0 < N_, r1v = n1 < N_;
    int i1a = n0 / WS_, j1a = n0 - i1a * WS_;
    int i1b = n1 / WS_, j1b = n1 - i1b * WS_;
#pragma unroll
    for (int ni = 0; ni < 8; ni++) {
        int m0 = ni * 8 + 2 * lc, m1 = m0 + 1;
        int i20 = m0 / WS_, j20 = m0 - i20 * WS_;
        int i21 = m1 / WS_, j21 = m1 - i21 * WS_;
        bool c0v = m0 < N_, c1v = m1 < N_;
        c[ni][0] = (r0v && c0v)
            ? c[ni][0] * scale + rpbs[(i1a - i20 + 6) * 13 + (j1a - j20 + 6)]
                + mrow[n0 * N_ + m0] : -1e30f;
        c[ni][1] = (r0v && c1v)
            ? c[ni][1] * scale + rpbs[(i1a - i21 + 6) * 13 + (j1a - j21 + 6)]
                + mrow[n0 * N_ + m1] : -1e30f;
        c[ni][2] = (r1v && c0v)
            ? c[ni][2] * scale + rpbs[(i1b - i20 + 6) * 13 + (j1b - j20 + 6)]
                + mrow[n1 * N_ + m0] : -1e30f;
        c[ni][3] = (r1v && c1v)
            ? c[ni][3] * scale + rpbs[(i1b - i21 + 6) * 13 + (j1b - j21 + 6)]
                + mrow[n1 * N_ + m1] : -1e30f;
    }

    // ---- register softmax (row n0 = [0..1], row n1 = [2..3]); quad reduce
    float mx0 = -1e30f, mx1 = -1e30f;
#pragma unroll
    for (int ni = 0; ni < 8; ni++) {
        mx0 = fmaxf(mx0, fmaxf(c[ni][0], c[ni][1]));
        mx1 = fmaxf(mx1, fmaxf(c[ni][2], c[ni][3]));
    }
    mx0 = fmaxf(mx0, __shfl_xor_sync(0xffffffffu, mx0, 1));
    mx0 = fmaxf(mx0, __shfl_xor_sync(0xffffffffu, mx0, 2));
    mx1 = fmaxf(mx1, __shfl_xor_sync(0xffffffffu, mx1, 1));
    mx1 = fmaxf(mx1, __shfl_xor_sync(0xffffffffu, mx1, 2));
    float s0 = 0.f, s1 = 0.f;
#pragma unroll
    for (int ni = 0; ni < 8; ni++) {
        c[ni][0] = __expf(c[ni][0] - mx0); s0 += c[ni][0];
        c[ni][1] = __expf(c[ni][1] - mx0); s0 += c[ni][1];
        c[ni][2] = __expf(c[ni][2] - mx1); s1 += c[ni][2];
        c[ni][3] = __expf(c[ni][3] - mx1); s1 += c[ni][3];
    }
    s0 += __shfl_xor_sync(0xffffffffu, s0, 1);
    s0 += __shfl_xor_sync(0xffffffffu, s0, 2);
    s1 += __shfl_xor_sync(0xffffffffu, s1, 1);
    s1 += __shfl_xor_sync(0xffffffffu, s1, 2);
    float inv0 = 1.f / s0, inv1 = 1.f / s1;

    // ---- pack P into A-operand frags (accumulator layout == A layout)
    uint32_t pa[4][4];
#pragma unroll
    for (int kt = 0; kt < 4; kt++) {
        pa[kt][0] = packbf(c[2 * kt][0] * inv0,     c[2 * kt][1] * inv0);
        pa[kt][1] = packbf(c[2 * kt][2] * inv1,     c[2 * kt][3] * inv1);
        pa[kt][2] = packbf(c[2 * kt + 1][0] * inv0, c[2 * kt + 1][1] * inv0);
        pa[kt][3] = packbf(c[2 * kt + 1][2] * inv1, c[2 * kt + 1][3] * inv1);
    }

    // ---- PV: rows [warp*16,+16) x 32 d, K = 64 (pad keys/cols are 0)
    float o[4][4];
#pragma unroll
    for (int i = 0; i < 4; i++)
#pragma unroll
        for (int q = 0; q < 4; q++) o[i][q] = 0.f;
#pragma unroll
    for (int kt = 0; kt < 4; kt++) {
#pragma unroll
        for (int ni = 0; ni < 4; ni++) {
            uint32_t b[2];
            ldsm_x2(b, vtb + (uint32_t)((ni * 8 + lrow) * AP_P + kt * 16 + b_k) * 2);
            mma_bf16(o[ni], pa[kt], b);
        }
    }
    __nv_bfloat16* ob = g_attno + (size_t)win * N_ * C_ + head * HD_;
#pragma unroll
    for (int ni = 0; ni < 4; ni++) {
#pragma unroll
        for (int half = 0; half < 2; half++) {
            int row = warp * 16 + lr + half * 8;
            if (row < N_) {
                int col = ni * 8 + 2 * lc;
                *(__nv_bfloat162*)(ob + (size_t)row * C_ + col) =
                    __floats2bfloat162_rn(o[ni][half * 2], o[ni][half * 2 + 1]);
            }
        }
    }
}

// ----------------------------------------------------------------
extern "C" void kernel_launch(void* const* d_in, const int* in_sizes, int n_in,
                              void* d_out, int out_size)
{
    const float* x     = (const float*)d_in[0];
    const float* mask  = (const float*)d_in[1];
    const float* ln1g  = (const float*)d_in[2];
    const float* ln1b  = (const float*)d_in[3];
    const float* qkvw  = (const float*)d_in[4];
    const float* qkvb  = (const float*)d_in[5];
    const float* rpb   = (const float*)d_in[6];
    const float* projw = (const float*)d_in[7];
    const float* projb = (const float*)d_in[8];
    const float* ln2g  = (const float*)d_in[9];
    const float* ln2b  = (const float*)d_in[10];
    const float* fc1w  = (const float*)d_in[11];
    const float* fc1b  = (const float*)d_in[12];
    const float* fc2w  = (const float*)d_in[13];
    const float* fc2b  = (const float*)d_in[14];
    float* out = (float*)d_out;

    __nv_bfloat16 *hwin, *qkv, *attno, *ln2, *hid;
    __nv_bfloat16 *qkvwT, *projT, *fc1T, *fc2T;
    float *x1;
    cudaGetSymbolAddress((void**)&hwin,  g_hwin);
    cudaGetSymbolAddress((void**)&qkv,   g_qkv);
    cudaGetSymbolAddress((void**)&attno, g_attno);
    cudaGetSymbolAddress((void**)&x1,    g_x1);
    cudaGetSymbolAddress((void**)&ln2,   g_ln2);
    cudaGetSymbolAddress((void**)&hid,   g_hid);
    cudaGetSymbolAddress((void**)&qkvwT, g_qkvwT);
    cudaGetSymbolAddress((void**)&projT, g_projT);
    cudaGetSymbolAddress((void**)&fc1T,  g_fc1T);
    cudaGetSymbolAddress((void**)&fc2T,  g_fc2T);

    cudaFuncSetAttribute(gemm_mma<0>, cudaFuncAttributeMaxDynamicSharedMemorySize, SMEM_BYTES);
    cudaFuncSetAttribute(gemm_mma<1>, cudaFuncAttributeMaxDynamicSharedMemorySize, SMEM_BYTES);
    cudaFuncSetAttribute(gemm_mma<2>, cudaFuncAttributeMaxDynamicSharedMemorySize, SMEM_BYTES);
    cudaFuncSetAttribute(gemm_mma<3>, cudaFuncAttributeMaxDynamicSharedMemorySize, SMEM_BYTES);

    // 0) merged weight convert + transpose (1 launch, 432 tiles)
    wprep_all<<<432, dim3(32, 8)>>>(qkvw, projw, fc1w, fc2w,
                                    qkvwT, projT, fc1T, fc2T);

    const int ln_grid = TOK / 8;

    // 1) LN1 + shift + window partition -> bf16
    ln_kernel<1><<<ln_grid, 256>>>(x, hwin, ln1g, ln1b);

    // 2) QKV GEMM -> bf16
    gemm_mma<0><<<dim3(TOK / BM, C3 / BN), 256, SMEM_BYTES>>>(
        hwin, qkvwT, qkvb, nullptr, qkv, TOK, C3, C_);

    // 3) Windowed attention (register softmax, 1 barrier) -> bf16
    attn_kernel<<<dim3(WINS, NH_), 128>>>(rpb, mask);

    // 4) proj + window reverse + fp32 residual -> x1 (fp32)
    gemm_mma<1><<<dim3(TOK / BM, C_ / BN), 256, SMEM_BYTES>>>(
        attno, projT, projb, x, x1, TOK, C_, C_);

    // 5) LN2 -> bf16
    ln_kernel<0><<<ln_grid, 256>>>(x1, ln2, ln2g, ln2b);

    // 6) FC1 + GELU -> bf16
    gemm_mma<2><<<dim3(TOK / BM, HID_ / BN), 256, SMEM_BYTES>>>(
        ln2, fc1T, fc1b, nullptr, hid, TOK, HID_, C_);

    // 7) FC2 + fp32 residual -> out (fp32)
    gemm_mma<3><<<dim3(TOK / BM, C_ / BN), 256, SMEM_BYTES>>>(
        hid, fc2T, fc2b, x1, out, TOK, C_, HID_);
}